// round 7
// baseline (speedup 1.0000x reference)
#include <cuda_runtime.h>
#include <math.h>

#define UNROLL 8
#define TPB 256
#define NUM_SMS 148
#define BLOCKS_PER_SM 4           // matches measured residency at ~62 regs
#define GRID (NUM_SMS * BLOCKS_PER_SM)

// ---------------------------------------------------------------------------
// Persistent fused kernel (single wave, grid-stride over tiles).
// Thread 0 of each block computes the 3x4 affine transform
//   M[i][j] = scale[j] * (se3_exp_rot(tau) @ R)[i][j],  M[i][3] = T[i] + dt[i]
// (column scaling per numpy broadcast over last axis), then all threads
// stream y = M @ x, 8 coalesced float4s per thread per tile, streaming
// (evict-first) cache hints — zero data reuse.
// ---------------------------------------------------------------------------
__global__ void __launch_bounds__(TPB) fused_kernel(
    const float4* __restrict__ x,
    float4* __restrict__ y,
    const float* __restrict__ rot_delta,
    const float* __restrict__ trans_delta,
    const float* __restrict__ scale,
    const float* __restrict__ Rin,
    const float* __restrict__ Tin,
    int n4)
{
    __shared__ float4 sM[3];

    if (threadIdx.x == 0) {
        float tx = rot_delta[0], ty = rot_delta[1], tz = rot_delta[2];
        float rx = trans_delta[0], ry = trans_delta[1], rz = trans_delta[2];

        float angle = sqrtf(tx * tx + ty * ty + tz * tz);
        bool small = angle < 1e-5f;
        float a = small ? 1.0f : angle;

        float sa = sinf(a);
        float ca = cosf(a);
        float A = small ? 1.0f : (sa / a);
        float B = small ? 0.5f : ((1.0f - ca) / (a * a));
        float C = small ? (1.0f / 6.0f) : ((a - sa) / (a * a * a));

        float W[9] = { 0.0f, -tz,  ty,
                       tz,  0.0f, -tx,
                      -ty,   tx, 0.0f };
        float W2[9];
        #pragma unroll
        for (int i = 0; i < 3; i++)
            #pragma unroll
            for (int j = 0; j < 3; j++) {
                float s = 0.0f;
                #pragma unroll
                for (int k = 0; k < 3; k++) s += W[i * 3 + k] * W[k * 3 + j];
                W2[i * 3 + j] = s;
            }

        float dR[9], Vm[9];
        #pragma unroll
        for (int i = 0; i < 9; i++) {
            float I = (i % 4 == 0) ? 1.0f : 0.0f;
            dR[i] = I + A * W[i] + B * W2[i];
            Vm[i] = I + B * W[i] + C * W2[i];
        }

        float dt[3];
        #pragma unroll
        for (int i = 0; i < 3; i++)
            dt[i] = Vm[i * 3 + 0] * rx + Vm[i * 3 + 1] * ry + Vm[i * 3 + 2] * rz;

        #pragma unroll
        for (int i = 0; i < 3; i++) {
            float row[4];
            #pragma unroll
            for (int j = 0; j < 3; j++) {
                float s = 0.0f;
                #pragma unroll
                for (int k = 0; k < 3; k++) s += dR[i * 3 + k] * Rin[k * 3 + j];
                row[j] = scale[j] * s;
            }
            row[3] = Tin[i] + dt[i];
            sM[i] = make_float4(row[0], row[1], row[2], row[3]);
        }
    }
    __syncthreads();

    float4 r0 = sM[0];
    float4 r1 = sM[1];
    float4 r2 = sM[2];

    const int tile_elems = TPB * UNROLL;
    const int n_tiles = (n4 + tile_elems - 1) / tile_elems;

    for (int tile = blockIdx.x; tile < n_tiles; tile += gridDim.x) {
        int base = tile * tile_elems + threadIdx.x;

        if (base + (UNROLL - 1) * TPB < n4) {
            // Fast path: whole tile in range.
            float4 v[UNROLL];
            #pragma unroll
            for (int u = 0; u < UNROLL; u++)
                v[u] = __ldcs(&x[base + u * TPB]);

            #pragma unroll
            for (int u = 0; u < UNROLL; u++) {
                float4 p = v[u];
                float4 o;
                o.x = fmaf(r0.x, p.x, fmaf(r0.y, p.y, fmaf(r0.z, p.z, r0.w * p.w)));
                o.y = fmaf(r1.x, p.x, fmaf(r1.y, p.y, fmaf(r1.z, p.z, r1.w * p.w)));
                o.z = fmaf(r2.x, p.x, fmaf(r2.y, p.y, fmaf(r2.z, p.z, r2.w * p.w)));
                o.w = p.w;
                __stcs(&y[base + u * TPB], o);
            }
        } else {
            // Tail path: per-element bounds check.
            #pragma unroll
            for (int u = 0; u < UNROLL; u++) {
                int i = base + u * TPB;
                if (i < n4) {
                    float4 p = __ldcs(&x[i]);
                    float4 o;
                    o.x = fmaf(r0.x, p.x, fmaf(r0.y, p.y, fmaf(r0.z, p.z, r0.w * p.w)));
                    o.y = fmaf(r1.x, p.x, fmaf(r1.y, p.y, fmaf(r1.z, p.z, r1.w * p.w)));
                    o.z = fmaf(r2.x, p.x, fmaf(r2.y, p.y, fmaf(r2.z, p.z, r2.w * p.w)));
                    o.w = p.w;
                    __stcs(&y[i], o);
                }
            }
        }
    }
}

extern "C" void kernel_launch(void* const* d_in, const int* in_sizes, int n_in,
                              void* d_out, int out_size)
{
    const float* x          = (const float*)d_in[0];   // (N,4)
    const float* rot_delta  = (const float*)d_in[1];   // (3,)
    const float* trans_delta= (const float*)d_in[2];   // (3,)
    const float* scale      = (const float*)d_in[3];   // (3,)
    const float* R          = (const float*)d_in[4];   // (3,3)
    const float* T          = (const float*)d_in[5];   // (3,)
    float* out = (float*)d_out;

    int n4 = in_sizes[0] / 4;   // number of points (float4 elements)

    fused_kernel<<<GRID, TPB>>>((const float4*)x, (float4*)out,
                                rot_delta, trans_delta, scale, R, T, n4);
}

// round 8
// speedup vs baseline: 1.1225x; 1.1225x over previous
#include <cuda_runtime.h>
#include <math.h>

#define UNROLL 8
#define TPB 256

// ---------------------------------------------------------------------------
// Fused kernel: thread 0 of each block computes the 3x4 affine transform
//   M[i][j] = scale[j] * (se3_exp_rot(tau) @ R)[i][j],  M[i][3] = T[i] + dt[i]
// (column scaling per numpy broadcast over last axis), then all threads
// stream y = M @ x with 8 coalesced float4s per thread using streaming
// (evict-first) cache hints — data has zero reuse.
//
// Full oversubscribed grid (one tile per block): on B300 the work-stealing
// wave scheduler makes CTA launch the cheapest pipelining mechanism; a
// persistent single-wave variant measured 12% SLOWER (DRAM 80.6% -> 74%).
// ---------------------------------------------------------------------------
__global__ void __launch_bounds__(TPB) fused_kernel(
    const float4* __restrict__ x,
    float4* __restrict__ y,
    const float* __restrict__ rot_delta,
    const float* __restrict__ trans_delta,
    const float* __restrict__ scale,
    const float* __restrict__ Rin,
    const float* __restrict__ Tin,
    int n4)
{
    __shared__ float4 sM[3];

    if (threadIdx.x == 0) {
        float tx = rot_delta[0], ty = rot_delta[1], tz = rot_delta[2];
        float rx = trans_delta[0], ry = trans_delta[1], rz = trans_delta[2];

        float angle = sqrtf(tx * tx + ty * ty + tz * tz);
        bool small = angle < 1e-5f;
        float a = small ? 1.0f : angle;

        float sa = sinf(a);
        float ca = cosf(a);
        float A = small ? 1.0f : (sa / a);
        float B = small ? 0.5f : ((1.0f - ca) / (a * a));
        float C = small ? (1.0f / 6.0f) : ((a - sa) / (a * a * a));

        float W[9] = { 0.0f, -tz,  ty,
                       tz,  0.0f, -tx,
                      -ty,   tx, 0.0f };
        float W2[9];
        #pragma unroll
        for (int i = 0; i < 3; i++)
            #pragma unroll
            for (int j = 0; j < 3; j++) {
                float s = 0.0f;
                #pragma unroll
                for (int k = 0; k < 3; k++) s += W[i * 3 + k] * W[k * 3 + j];
                W2[i * 3 + j] = s;
            }

        float dR[9], Vm[9];
        #pragma unroll
        for (int i = 0; i < 9; i++) {
            float I = (i % 4 == 0) ? 1.0f : 0.0f;
            dR[i] = I + A * W[i] + B * W2[i];
            Vm[i] = I + B * W[i] + C * W2[i];
        }

        float dt[3];
        #pragma unroll
        for (int i = 0; i < 3; i++)
            dt[i] = Vm[i * 3 + 0] * rx + Vm[i * 3 + 1] * ry + Vm[i * 3 + 2] * rz;

        #pragma unroll
        for (int i = 0; i < 3; i++) {
            float row[4];
            #pragma unroll
            for (int j = 0; j < 3; j++) {
                float s = 0.0f;
                #pragma unroll
                for (int k = 0; k < 3; k++) s += dR[i * 3 + k] * Rin[k * 3 + j];
                row[j] = scale[j] * s;
            }
            row[3] = Tin[i] + dt[i];
            sM[i] = make_float4(row[0], row[1], row[2], row[3]);
        }
    }
    __syncthreads();

    float4 r0 = sM[0];
    float4 r1 = sM[1];
    float4 r2 = sM[2];

    int base = blockIdx.x * (TPB * UNROLL) + threadIdx.x;

    if (base + (UNROLL - 1) * TPB < n4) {
        // Fast path: whole tile in range (all blocks when N % (TPB*UNROLL)==0).
        float4 v[UNROLL];
        #pragma unroll
        for (int u = 0; u < UNROLL; u++)
            v[u] = __ldcs(&x[base + u * TPB]);

        #pragma unroll
        for (int u = 0; u < UNROLL; u++) {
            float4 p = v[u];
            float4 o;
            o.x = fmaf(r0.x, p.x, fmaf(r0.y, p.y, fmaf(r0.z, p.z, r0.w * p.w)));
            o.y = fmaf(r1.x, p.x, fmaf(r1.y, p.y, fmaf(r1.z, p.z, r1.w * p.w)));
            o.z = fmaf(r2.x, p.x, fmaf(r2.y, p.y, fmaf(r2.z, p.z, r2.w * p.w)));
            o.w = p.w;
            __stcs(&y[base + u * TPB], o);
        }
    } else {
        // Tail path: per-element bounds check.
        #pragma unroll
        for (int u = 0; u < UNROLL; u++) {
            int i = base + u * TPB;
            if (i < n4) {
                float4 p = __ldcs(&x[i]);
                float4 o;
                o.x = fmaf(r0.x, p.x, fmaf(r0.y, p.y, fmaf(r0.z, p.z, r0.w * p.w)));
                o.y = fmaf(r1.x, p.x, fmaf(r1.y, p.y, fmaf(r1.z, p.z, r1.w * p.w)));
                o.z = fmaf(r2.x, p.x, fmaf(r2.y, p.y, fmaf(r2.z, p.z, r2.w * p.w)));
                o.w = p.w;
                __stcs(&y[i], o);
            }
        }
    }
}

extern "C" void kernel_launch(void* const* d_in, const int* in_sizes, int n_in,
                              void* d_out, int out_size)
{
    const float* x          = (const float*)d_in[0];   // (N,4)
    const float* rot_delta  = (const float*)d_in[1];   // (3,)
    const float* trans_delta= (const float*)d_in[2];   // (3,)
    const float* scale      = (const float*)d_in[3];   // (3,)
    const float* R          = (const float*)d_in[4];   // (3,3)
    const float* T          = (const float*)d_in[5];   // (3,)
    float* out = (float*)d_out;

    int n4 = in_sizes[0] / 4;   // number of points (float4 elements)

    int elems_per_block = TPB * UNROLL;
    int blocks = (n4 + elems_per_block - 1) / elems_per_block;

    fused_kernel<<<blocks, TPB>>>((const float4*)x, (float4*)out,
                                  rot_delta, trans_delta, scale, R, T, n4);
}